// round 3
// baseline (speedup 1.0000x reference)
#include <cuda_runtime.h>
#include <math.h>

// ---------------------------------------------------------------------------
// GATNet: 2-layer GAT (heads=8,out=8 concat + ELU; heads=1,out=10 + log_softmax)
// N=100000, E=1600000 (+N self loops), F_IN=512.
// fp32 tiled GEMM for x@W1; per-launch CSR build so segment-softmax +
// aggregation run warp-per-dst-node with zero float atomics (h1 L2-resident).
// edge_index dtype (int32 vs int64) detected at runtime on-device.
// ---------------------------------------------------------------------------

#define MAXN 100352
#define MAXE 1700000
#define HEADS 8
#define NCOUT 10
#define FULLMASK 0xffffffffu

__device__ __align__(16) float g_h1[MAXN * 64];
__device__ __align__(16) float g_as1[MAXN * HEADS];
__device__ __align__(16) float g_ad1[MAXN * HEADS];
__device__ __align__(16) float g_agg1[MAXN * 64];
__device__ __align__(16) float g_h2[MAXN * NCOUT];
__device__ float g_as2[MAXN];
__device__ float g_ad2[MAXN];
__device__ int   g_deg[MAXN];
__device__ int   g_rowptr[MAXN + 1];
__device__ int   g_cursor[MAXN];
__device__ int   g_col[MAXE + MAXN];
__device__ int   g_bsum[256];
__device__ int   g_boff[256];
__device__ int   g_is32;

// ---------------------------------------------------------------------------
// dtype detection: int64 node ids in [0,N) vs int32 pairs fused into int64.
// ---------------------------------------------------------------------------
__global__ void detect_kernel(const void* __restrict__ ei, int N)
{
    if (threadIdx.x == 0 && blockIdx.x == 0) {
        const long long* p = (const long long*)ei;
        int is32 = 0;
        for (int i = 0; i < 256; i++) {
            long long v = p[i];
            if (v < 0 || v >= (long long)N) { is32 = 1; break; }
        }
        g_is32 = is32;
    }
}

__device__ __forceinline__ int edge_at(const void* ei, int is32, size_t idx)
{
    return is32 ? ((const int*)ei)[idx] : (int)((const long long*)ei)[idx];
}

// ---------------------------------------------------------------------------
// GEMM1: C[N,64] = A[N,K]*B[K,64]. BM=128, BN=64, BK=16; 256 thr, 8x4/thread.
// ---------------------------------------------------------------------------
__global__ __launch_bounds__(256) void gemm1_kernel(
    const float* __restrict__ A, const float* __restrict__ B, int N, int K)
{
    __shared__ float As[16][128 + 4];
    __shared__ float Bs[16][64];

    const int tid = threadIdx.x;
    const int row0 = blockIdx.x * 128;
    const int tx = tid & 15;
    const int ty = tid >> 4;

    float acc[8][4];
#pragma unroll
    for (int i = 0; i < 8; i++)
#pragma unroll
        for (int j = 0; j < 4; j++) acc[i][j] = 0.f;

    for (int kt = 0; kt < K; kt += 16) {
#pragma unroll
        for (int l = 0; l < 2; l++) {
            int idx = tid * 2 + l;
            int r = idx >> 2;
            int c4 = (idx & 3) * 4;
            float4 v = make_float4(0.f, 0.f, 0.f, 0.f);
            if (row0 + r < N)
                v = *(const float4*)&A[(size_t)(row0 + r) * K + kt + c4];
            As[c4 + 0][r] = v.x;
            As[c4 + 1][r] = v.y;
            As[c4 + 2][r] = v.z;
            As[c4 + 3][r] = v.w;
        }
        {
            int r = tid >> 4;
            int c4 = (tid & 15) * 4;
            *(float4*)&Bs[r][c4] = *(const float4*)&B[(size_t)(kt + r) * 64 + c4];
        }
        __syncthreads();

#pragma unroll
        for (int k = 0; k < 16; k++) {
            float4 a0 = *(const float4*)&As[k][ty * 8];
            float4 a1 = *(const float4*)&As[k][ty * 8 + 4];
            float4 b  = *(const float4*)&Bs[k][tx * 4];
            float av[8] = {a0.x, a0.y, a0.z, a0.w, a1.x, a1.y, a1.z, a1.w};
            float bv[4] = {b.x, b.y, b.z, b.w};
#pragma unroll
            for (int i = 0; i < 8; i++)
#pragma unroll
                for (int j = 0; j < 4; j++)
                    acc[i][j] = fmaf(av[i], bv[j], acc[i][j]);
        }
        __syncthreads();
    }

#pragma unroll
    for (int i = 0; i < 8; i++) {
        int r = row0 + ty * 8 + i;
        if (r < N)
            *(float4*)&g_h1[(size_t)r * 64 + tx * 4] =
                make_float4(acc[i][0], acc[i][1], acc[i][2], acc[i][3]);
    }
}

// ---------------------------------------------------------------------------
__global__ void alpha1_kernel(const float* __restrict__ asrc,
                              const float* __restrict__ adst, int N)
{
    int t = blockIdx.x * blockDim.x + threadIdx.x;
    if (t >= N * HEADS) return;
    int n = t >> 3, hd = t & 7;
    const float* row = &g_h1[(size_t)n * 64 + hd * 8];
    float s = 0.f, d = 0.f;
#pragma unroll
    for (int c = 0; c < 8; c++) {
        float v = row[c];
        s = fmaf(v, __ldg(&asrc[hd * 8 + c]), s);
        d = fmaf(v, __ldg(&adst[hd * 8 + c]), d);
    }
    g_as1[t] = s;
    g_ad1[t] = d;
}

// ---------------------------------------------------------------------------
// CSR build
// ---------------------------------------------------------------------------
__global__ void zero_deg_kernel(int N)
{
    int n = blockIdx.x * blockDim.x + threadIdx.x;
    if (n < N) g_deg[n] = 0;
}

__global__ void count_kernel(const void* __restrict__ ei, int E, int N)
{
    int e = blockIdx.x * blockDim.x + threadIdx.x;
    if (e >= E) return;
    int d = edge_at(ei, g_is32, (size_t)E + e);
    if (d >= 0 && d < N) atomicAdd(&g_deg[d], 1);
}

__global__ void scan1_kernel(int N)
{
    __shared__ int sh[1024];
    int b = blockIdx.x, t = threadIdx.x;
    int g = b * 1024 + t;
    int v = (g < N) ? (g_deg[g] + 1) : 0;
    sh[t] = v;
    __syncthreads();
    for (int off = 1; off < 1024; off <<= 1) {
        int add = (t >= off) ? sh[t - off] : 0;
        __syncthreads();
        sh[t] += add;
        __syncthreads();
    }
    if (g < N) g_rowptr[g] = sh[t] - v;
    if (t == 1023) g_bsum[b] = sh[1023];
}

__global__ void scan2_kernel(int nb, int N)
{
    if (threadIdx.x == 0 && blockIdx.x == 0) {
        int run = 0;
        for (int i = 0; i < nb; i++) { g_boff[i] = run; run += g_bsum[i]; }
        g_rowptr[N] = run;
    }
}

__global__ void scan3_kernel(int N)
{
    int g = blockIdx.x * blockDim.x + threadIdx.x;
    if (g < N) {
        int r = g_rowptr[g] + g_boff[g >> 10];
        g_rowptr[g] = r;
        g_cursor[g] = r;
    }
}

__global__ void fill_edges_kernel(const void* __restrict__ ei, int E, int N)
{
    int e = blockIdx.x * blockDim.x + threadIdx.x;
    if (e >= E) return;
    int is32 = g_is32;
    int s = edge_at(ei, is32, (size_t)e);
    int d = edge_at(ei, is32, (size_t)E + e);
    if (s < 0 || s >= N || d < 0 || d >= N) return;
    int pos = atomicAdd(&g_cursor[d], 1);
    g_col[pos] = s;
}

__global__ void fill_self_kernel(int N)
{
    int n = blockIdx.x * blockDim.x + threadIdx.x;
    if (n >= N) return;
    int pos = atomicAdd(&g_cursor[n], 1);
    g_col[pos] = n;
}

// ---------------------------------------------------------------------------
// attn1: warp per dst node; zero atomics.
// ---------------------------------------------------------------------------
__device__ __forceinline__ float lrelu(float z) { return z > 0.f ? z : 0.2f * z; }

__global__ __launch_bounds__(256) void attn1_kernel(const float* __restrict__ b1, int N)
{
    int warp = (blockIdx.x * blockDim.x + threadIdx.x) >> 5;
    int lane = threadIdx.x & 31;
    if (warp >= N) return;
    int n = warp;
    int beg = g_rowptr[n], end = g_rowptr[n + 1];

    float4 adA = *(const float4*)&g_ad1[(size_t)n * 8];
    float4 adB = *(const float4*)&g_ad1[(size_t)n * 8 + 4];

    float mx[8];
#pragma unroll
    for (int h = 0; h < 8; h++) mx[h] = -1e30f;

    for (int i = beg + lane; i < end; i += 32) {
        int s = g_col[i];
        float4 a0 = *(const float4*)&g_as1[(size_t)s * 8];
        float4 a1 = *(const float4*)&g_as1[(size_t)s * 8 + 4];
        mx[0] = fmaxf(mx[0], lrelu(a0.x + adA.x));
        mx[1] = fmaxf(mx[1], lrelu(a0.y + adA.y));
        mx[2] = fmaxf(mx[2], lrelu(a0.z + adA.z));
        mx[3] = fmaxf(mx[3], lrelu(a0.w + adA.w));
        mx[4] = fmaxf(mx[4], lrelu(a1.x + adB.x));
        mx[5] = fmaxf(mx[5], lrelu(a1.y + adB.y));
        mx[6] = fmaxf(mx[6], lrelu(a1.z + adB.z));
        mx[7] = fmaxf(mx[7], lrelu(a1.w + adB.w));
    }
#pragma unroll
    for (int off = 16; off; off >>= 1)
#pragma unroll
        for (int h = 0; h < 8; h++)
            mx[h] = fmaxf(mx[h], __shfl_xor_sync(FULLMASK, mx[h], off));

    int f0 = lane * 2;
    int head = lane >> 2;
    float mh = (head < 4)
        ? ((head < 2) ? (head == 0 ? mx[0] : mx[1]) : (head == 2 ? mx[2] : mx[3]))
        : ((head < 6) ? (head == 4 ? mx[4] : mx[5]) : (head == 6 ? mx[6] : mx[7]));
    float adh = (head < 4)
        ? ((head < 2) ? (head == 0 ? adA.x : adA.y) : (head == 2 ? adA.z : adA.w))
        : ((head < 6) ? (head == 4 ? adB.x : adB.y) : (head == 6 ? adB.z : adB.w));

    float denom = 0.f, acc0 = 0.f, acc1 = 0.f;
    for (int i = beg; i < end; i++) {
        int s = g_col[i];
        float asv = __ldg(&g_as1[(size_t)s * 8 + head]);
        float p = __expf(lrelu(asv + adh) - mh);
        if ((lane & 3) == 0) denom += p;
        float2 hv = *(const float2*)&g_h1[(size_t)s * 64 + f0];
        acc0 = fmaf(p, hv.x, acc0);
        acc1 = fmaf(p, hv.y, acc1);
    }
    float dsum = __shfl_sync(FULLMASK, denom, lane & ~3);
    float inv = 1.f / (dsum + 1e-16f);
    float o0 = acc0 * inv + __ldg(&b1[f0]);
    float o1 = acc1 * inv + __ldg(&b1[f0 + 1]);
    o0 = o0 > 0.f ? o0 : (expf(o0) - 1.f);
    o1 = o1 > 0.f ? o1 : (expf(o1) - 1.f);
    *(float2*)&g_agg1[(size_t)n * 64 + f0] = make_float2(o0, o1);
}

// ---------------------------------------------------------------------------
__global__ __launch_bounds__(256) void gemm2_kernel(
    const float* __restrict__ W2, const float* __restrict__ asrc2,
    const float* __restrict__ adst2, int N)
{
    __shared__ float Ws[64 * NCOUT];
    for (int i = threadIdx.x; i < 64 * NCOUT; i += blockDim.x) Ws[i] = W2[i];
    __syncthreads();

    int warp = (blockIdx.x * blockDim.x + threadIdx.x) >> 5;
    int lane = threadIdx.x & 31;
    if (warp >= N) return;
    int n = warp;

    float a0 = g_agg1[(size_t)n * 64 + lane];
    float a1 = g_agg1[(size_t)n * 64 + 32 + lane];
    float s2 = 0.f, d2 = 0.f;
#pragma unroll
    for (int c = 0; c < NCOUT; c++) {
        float part = a0 * Ws[lane * NCOUT + c] + a1 * Ws[(lane + 32) * NCOUT + c];
#pragma unroll
        for (int off = 16; off; off >>= 1)
            part += __shfl_xor_sync(FULLMASK, part, off);
        if (lane == 0) g_h2[(size_t)n * NCOUT + c] = part;
        s2 = fmaf(part, __ldg(&asrc2[c]), s2);
        d2 = fmaf(part, __ldg(&adst2[c]), d2);
    }
    if (lane == 0) { g_as2[n] = s2; g_ad2[n] = d2; }
}

// ---------------------------------------------------------------------------
__global__ __launch_bounds__(256) void attn2_kernel(
    const float* __restrict__ b2, float* __restrict__ out, int N)
{
    int warp = (blockIdx.x * blockDim.x + threadIdx.x) >> 5;
    int lane = threadIdx.x & 31;
    if (warp >= N) return;
    int n = warp;
    int beg = g_rowptr[n], end = g_rowptr[n + 1];
    float adn = g_ad2[n];

    float mxv = -1e30f;
    for (int i = beg + lane; i < end; i += 32) {
        int s = g_col[i];
        mxv = fmaxf(mxv, lrelu(g_as2[s] + adn));
    }
#pragma unroll
    for (int off = 16; off; off >>= 1)
        mxv = fmaxf(mxv, __shfl_xor_sync(FULLMASK, mxv, off));

    float denom = 0.f;
    float acc[NCOUT];
#pragma unroll
    for (int c = 0; c < NCOUT; c++) acc[c] = 0.f;

    for (int i = beg + lane; i < end; i += 32) {
        int s = g_col[i];
        float p = __expf(lrelu(g_as2[s] + adn) - mxv);
        denom += p;
        const float* hr = &g_h2[(size_t)s * NCOUT];
#pragma unroll
        for (int c = 0; c < NCOUT; c += 2) {
            float2 hv = *(const float2*)&hr[c];
            acc[c]     = fmaf(p, hv.x, acc[c]);
            acc[c + 1] = fmaf(p, hv.y, acc[c + 1]);
        }
    }
#pragma unroll
    for (int off = 16; off; off >>= 1) {
        denom += __shfl_xor_sync(FULLMASK, denom, off);
#pragma unroll
        for (int c = 0; c < NCOUT; c++)
            acc[c] += __shfl_xor_sync(FULLMASK, acc[c], off);
    }

    float inv = 1.f / (denom + 1e-16f);
    float logit[NCOUT];
    float lm = -1e30f;
#pragma unroll
    for (int c = 0; c < NCOUT; c++) {
        logit[c] = acc[c] * inv + __ldg(&b2[c]);
        lm = fmaxf(lm, logit[c]);
    }
    float se = 0.f;
#pragma unroll
    for (int c = 0; c < NCOUT; c++) se += __expf(logit[c] - lm);
    float lse = lm + logf(se);
    if (lane == 0) {
#pragma unroll
        for (int c = 0; c < NCOUT; c++)
            out[(size_t)n * NCOUT + c] = logit[c] - lse;
    }
}

// ---------------------------------------------------------------------------
extern "C" void kernel_launch(void* const* d_in, const int* in_sizes, int n_in,
                              void* d_out, int out_size)
{
    const float* x     = (const float*)d_in[0];
    const float* W1    = (const float*)d_in[1];
    const float* asrc1 = (const float*)d_in[2];
    const float* adst1 = (const float*)d_in[3];
    const float* b1    = (const float*)d_in[4];
    const float* W2    = (const float*)d_in[5];
    const float* asrc2 = (const float*)d_in[6];
    const float* adst2 = (const float*)d_in[7];
    const float* b2    = (const float*)d_in[8];
    const void*  ei    = (const void*)d_in[9];
    float*       out   = (float*)d_out;

    const int K = in_sizes[1] / 64;   // 512
    const int N = in_sizes[0] / K;    // 100000
    const int E = in_sizes[9] / 2;    // 1600000

    detect_kernel<<<1, 32>>>(ei, N);

    gemm1_kernel<<<(N + 127) / 128, 256>>>(x, W1, N, K);
    alpha1_kernel<<<(N * HEADS + 255) / 256, 256>>>(asrc1, adst1, N);

    zero_deg_kernel<<<(N + 255) / 256, 256>>>(N);
    count_kernel<<<(E + 255) / 256, 256>>>(ei, E, N);
    int nb = (N + 1023) / 1024;
    scan1_kernel<<<nb, 1024>>>(N);
    scan2_kernel<<<1, 32>>>(nb, N);
    scan3_kernel<<<(N + 255) / 256, 256>>>(N);
    fill_edges_kernel<<<(E + 255) / 256, 256>>>(ei, E, N);
    fill_self_kernel<<<(N + 255) / 256, 256>>>(N);

    attn1_kernel<<<(N + 7) / 8, 256>>>(b1, N);
    gemm2_kernel<<<(N + 7) / 8, 256>>>(W2, asrc2, adst2, N);
    attn2_kernel<<<(N + 7) / 8, 256>>>(b2, out, N);
}